// round 7
// baseline (speedup 1.0000x reference)
#include <cuda_runtime.h>
#include <math.h>

#define T_ 2048
#define D_ 2048
#define H_ 16
#define KVH_ 4
#define HD_ 128
#define E_ 8
#define I_ 1024
#define TOPK_ 2

// ---------------- static scratch (no allocations allowed) ----------------
__device__ float g_xn  [(size_t)T_ * D_];
__device__ float g_q   [(size_t)T_ * H_ * HD_];
__device__ float g_k   [(size_t)T_ * KVH_ * HD_];
__device__ float g_v   [(size_t)T_ * KVH_ * HD_];
__device__ float g_attn[(size_t)T_ * H_ * HD_];
__device__ float g_h1  [(size_t)T_ * D_];
__device__ float g_xn2 [(size_t)T_ * D_];
__device__ float g_g   [(size_t)E_ * T_ * I_];
__device__ float g_y   [(size_t)E_ * T_ * D_];
__device__ int   g_cnt [E_];
__device__ int   g_idx [E_ * T_];
__device__ int   g_slot[T_ * TOPK_];
__device__ float g_wt  [T_ * TOPK_];

struct QKVParams {
    const float* B0; const float* B1; const float* B2;
    const float* bias0; const float* bias1; const float* bias2;
    float* C0; float* C1; float* C2;
    int N0, N1, N2;
};

// ---------------- tf32 mma helpers ----------------
__device__ __forceinline__ unsigned f2tf(float f) {
    unsigned r;
    asm("cvt.rna.tf32.f32 %0, %1;" : "=r"(r) : "f"(f));
    return r;
}

__device__ __forceinline__ void mma_tf32(float c[4],
                                         unsigned a0, unsigned a1, unsigned a2, unsigned a3,
                                         unsigned b0, unsigned b1)
{
    asm volatile("mma.sync.aligned.m16n8k8.row.col.f32.tf32.tf32.f32 "
                 "{%0,%1,%2,%3}, {%4,%5,%6,%7}, {%8,%9}, {%0,%1,%2,%3};"
                 : "+f"(c[0]), "+f"(c[1]), "+f"(c[2]), "+f"(c[3])
                 : "r"(a0), "r"(a1), "r"(a2), "r"(a3), "r"(b0), "r"(b1));
}

__device__ __forceinline__ void cp16(unsigned dst, const void* src, bool pred) {
    int sz = pred ? 16 : 0;
    asm volatile("cp.async.cg.shared.global [%0], [%1], 16, %2;"
                 :: "r"(dst), "l"(src), "r"(sz));
}
__device__ __forceinline__ void cp_commit() { asm volatile("cp.async.commit_group;"); }
template<int N>
__device__ __forceinline__ void cp_wait() { asm volatile("cp.async.wait_group %0;" :: "n"(N)); }

// ---------------- tf32 tensor-core GEMM: 128x128x16, 256 thr (R3 known-good) ----------------
// C[m,n] = sum_k A[m,k] * B[k,n]   (B row-major K x N)
// GATHER: A rows indexed via gidx[z*T_ + m]
// MULTI:  z in {0,1,2} selects (B, bias, C, N) from mp; ldb=ldc=N
// SILU:   epilogue: C[m,n] = silu(C[m,n]) * acc   (read-modify-write)
#define A_PITCH 20      // 16 k + 4 pad
#define B_PITCH 136     // 128 n + 8 pad
#define ABUF (128 * A_PITCH)
#define BBUF (16 * B_PITCH)

template<bool GATHER, bool MULTI, bool SILU>
__global__ __launch_bounds__(256)
void gemm_kernel(const float* __restrict__ A, int lda, long sA,
                 const float* __restrict__ B, int ldb, long sB,
                 const float* __restrict__ bias,
                 float* __restrict__ C, int ldc, long sC,
                 int M, int N, int Kd,
                 const int* __restrict__ cnt, const int* __restrict__ gidx,
                 QKVParams mp)
{
    int z = blockIdx.z;
    if (MULTI) {
        if (z == 0)      { B = mp.B0; bias = mp.bias0; C = mp.C0; N = mp.N0; }
        else if (z == 1) { B = mp.B1; bias = mp.bias1; C = mp.C1; N = mp.N1; }
        else             { B = mp.B2; bias = mp.bias2; C = mp.C2; N = mp.N2; }
        ldb = N; ldc = N;
    } else {
        A += (long)z * sA;
        B += (long)z * sB;
        C += (long)z * sC;
        if (cnt) M = cnt[z];
    }
    const int* rows = GATHER ? (gidx + z * T_) : nullptr;

    int m0 = blockIdx.y * 128;
    int n0 = blockIdx.x * 128;
    if (m0 >= M || n0 >= N) return;

    __shared__ float As[2][ABUF];
    __shared__ float Bs[2][BBUF];

    int tid = threadIdx.x;
    int qa0 = tid, qa1 = tid + 256;

    int aM0 = qa0 >> 2, aK0 = (qa0 & 3) * 4;
    int aM1 = qa1 >> 2, aK1 = (qa1 & 3) * 4;
    bool aok0 = (m0 + aM0) < M;
    bool aok1 = (m0 + aM1) < M;
    long arow0 = 0, arow1 = 0;
    if (aok0) arow0 = GATHER ? (long)rows[m0 + aM0] : (long)(m0 + aM0);
    if (aok1) arow1 = GATHER ? (long)rows[m0 + aM1] : (long)(m0 + aM1);

    int bR0 = qa0 >> 5, bC0 = (qa0 & 31) * 4;
    int bR1 = qa1 >> 5, bC1 = (qa1 & 31) * 4;

    unsigned asb = (unsigned)__cvta_generic_to_shared(&As[0][0]);
    unsigned bsb = (unsigned)__cvta_generic_to_shared(&Bs[0][0]);
    unsigned adst0 = asb + (aM0 * A_PITCH + aK0) * 4;
    unsigned adst1 = asb + (aM1 * A_PITCH + aK1) * 4;
    unsigned bdst0 = bsb + (bR0 * B_PITCH + bC0) * 4;
    unsigned bdst1 = bsb + (bR1 * B_PITCH + bC1) * 4;

    float acc[4][4][4];
#pragma unroll
    for (int i = 0; i < 4; i++)
#pragma unroll
        for (int j = 0; j < 4; j++)
#pragma unroll
            for (int r = 0; r < 4; r++) acc[i][j][r] = 0.f;

    int wid = tid >> 5, lane = tid & 31;
    int lr = lane >> 2, lc = lane & 3;
    int wm = (wid & 1) * 64;
    int wn = (wid >> 1) * 32;

    const int KT = Kd >> 4;

    {
        cp16(adst0, A + arow0 * lda + aK0, aok0);
        cp16(adst1, A + arow1 * lda + aK1, aok1);
        cp16(bdst0, B + (long)bR0 * ldb + n0 + bC0, true);
        cp16(bdst1, B + (long)bR1 * ldb + n0 + bC1, true);
        cp_commit();
    }

    for (int kt = 0; kt < KT; kt++) {
        if (kt + 1 < KT) {
            int k0 = (kt + 1) << 4;
            unsigned off_a = ((kt + 1) & 1) * ABUF * 4;
            unsigned off_b = ((kt + 1) & 1) * BBUF * 4;
            cp16(adst0 + off_a, A + arow0 * lda + k0 + aK0, aok0);
            cp16(adst1 + off_a, A + arow1 * lda + k0 + aK1, aok1);
            cp16(bdst0 + off_b, B + (long)(k0 + bR0) * ldb + n0 + bC0, true);
            cp16(bdst1 + off_b, B + (long)(k0 + bR1) * ldb + n0 + bC1, true);
            cp_commit();
            cp_wait<1>();
        } else {
            cp_wait<0>();
        }
        __syncthreads();

        int buf = kt & 1;
        const float* Ab = As[buf];
        const float* Bb = Bs[buf];

#pragma unroll
        for (int kk = 0; kk < 16; kk += 8) {
            unsigned afr[4][4];
#pragma unroll
            for (int i = 0; i < 4; i++) {
                int mb = wm + i * 16;
                afr[i][0] = f2tf(Ab[(mb + lr)     * A_PITCH + kk + lc]);
                afr[i][1] = f2tf(Ab[(mb + lr + 8) * A_PITCH + kk + lc]);
                afr[i][2] = f2tf(Ab[(mb + lr)     * A_PITCH + kk + lc + 4]);
                afr[i][3] = f2tf(Ab[(mb + lr + 8) * A_PITCH + kk + lc + 4]);
            }
            unsigned bfr[4][2];
#pragma unroll
            for (int j = 0; j < 4; j++) {
                int nb = wn + j * 8;
                bfr[j][0] = f2tf(Bb[(kk + lc)     * B_PITCH + nb + lr]);
                bfr[j][1] = f2tf(Bb[(kk + lc + 4) * B_PITCH + nb + lr]);
            }
#pragma unroll
            for (int i = 0; i < 4; i++)
#pragma unroll
                for (int j = 0; j < 4; j++)
                    mma_tf32(acc[i][j], afr[i][0], afr[i][1], afr[i][2], afr[i][3],
                             bfr[j][0], bfr[j][1]);
        }
        __syncthreads();
    }

    // epilogue
#pragma unroll
    for (int i = 0; i < 4; i++) {
#pragma unroll
        for (int j = 0; j < 4; j++) {
            int m = m0 + wm + i * 16 + lr;
            int n = n0 + wn + j * 8 + lc * 2;
            float bv0 = 0.f, bv1 = 0.f;
            if (bias) { bv0 = bias[n]; bv1 = bias[n + 1]; }
            if (m < M) {
                float v0 = acc[i][j][0] + bv0, v1 = acc[i][j][1] + bv1;
                if (SILU) {
                    float2 g = *(float2*)&C[(long)m * ldc + n];
                    v0 = g.x / (1.f + __expf(-g.x)) * v0;
                    v1 = g.y / (1.f + __expf(-g.y)) * v1;
                }
                *(float2*)&C[(long)m * ldc + n] = make_float2(v0, v1);
            }
            if (m + 8 < M) {
                float v0 = acc[i][j][2] + bv0, v1 = acc[i][j][3] + bv1;
                if (SILU) {
                    float2 g = *(float2*)&C[(long)(m + 8) * ldc + n];
                    v0 = g.x / (1.f + __expf(-g.x)) * v0;
                    v1 = g.y / (1.f + __expf(-g.y)) * v1;
                }
                *(float2*)&C[(long)(m + 8) * ldc + n] = make_float2(v0, v1);
            }
        }
    }
}

// ---------------- flash attention (R3 verbatim — known good) ----------------
// Grid (16 qblocks, 16 heads), 256 thr (8 warps). Warp owns 16 rows x 128 cols.
// smem: Qs[128][132] | KVs[128][132] (K then V, reused) | Ps[128][132]
#define FP 132
#define FA_SMEM (3 * 128 * FP * 4)

__global__ __launch_bounds__(256)
void flash_attn_kernel(const float* __restrict__ q, const float* __restrict__ k,
                       const float* __restrict__ v, float* __restrict__ attn)
{
    int qi = blockIdx.x;
    int h  = blockIdx.y;
    int kvh = h >> 2;
    extern __shared__ float sm[];
    float* Qs  = sm;
    float* KVs = sm + 128 * FP;
    float* Ps  = sm + 2 * 128 * FP;

    int tid = threadIdx.x, wid = tid >> 5, lane = tid & 31;
    int lr = lane >> 2, lc = lane & 3;
    const float scale = 0.08838834764831845f;

    // load Q tile
    for (int i = tid; i < 128 * 32; i += 256) {
        int r = i >> 5, c4 = (i & 31) * 4;
        float4 val = *(const float4*)&q[((long)(qi * 128 + r) * H_ + h) * HD_ + c4];
        *(float4*)&Qs[r * FP + c4] = val;
    }

    float m_i[2] = {-1e30f, -1e30f};
    float l_i[2] = {0.f, 0.f};
    float o[16][4];
#pragma unroll
    for (int n = 0; n < 16; n++)
#pragma unroll
        for (int r = 0; r < 4; r++) o[n][r] = 0.f;

    int row0 = wid * 16 + lr;        // local rows: row0, row0+8
    int tg0 = qi * 128 + row0;
    int tg1 = tg0 + 8;

    for (int j = 0; j <= qi; j++) {
        __syncthreads();   // prior iter's V reads done (and Q stores on first iter)
        for (int i = tid; i < 128 * 32; i += 256) {
            int r = i >> 5, c4 = (i & 31) * 4;
            float4 val = *(const float4*)&k[((long)(j * 128 + r) * KVH_ + kvh) * HD_ + c4];
            *(float4*)&KVs[r * FP + c4] = val;
        }
        __syncthreads();

        // S = Q @ K^T
        float s[16][4];
#pragma unroll
        for (int n = 0; n < 16; n++)
#pragma unroll
            for (int r = 0; r < 4; r++) s[n][r] = 0.f;

#pragma unroll
        for (int kk = 0; kk < 128; kk += 8) {
            unsigned a0 = f2tf(Qs[row0 * FP + kk + lc]);
            unsigned a1 = f2tf(Qs[(row0 + 8) * FP + kk + lc]);
            unsigned a2 = f2tf(Qs[row0 * FP + kk + lc + 4]);
            unsigned a3 = f2tf(Qs[(row0 + 8) * FP + kk + lc + 4]);
#pragma unroll
            for (int n = 0; n < 16; n++) {
                unsigned b0 = f2tf(KVs[(n * 8 + lr) * FP + kk + lc]);
                unsigned b1 = f2tf(KVs[(n * 8 + lr) * FP + kk + lc + 4]);
                mma_tf32(s[n], a0, a1, a2, a3, b0, b1);
            }
        }

        // scale + causal mask (only diagonal block needs mask)
        if (j == qi) {
#pragma unroll
            for (int n = 0; n < 16; n++) {
                int c0 = j * 128 + n * 8 + lc * 2;
                s[n][0] = (c0     <= tg0) ? s[n][0] * scale : -1e30f;
                s[n][1] = (c0 + 1 <= tg0) ? s[n][1] * scale : -1e30f;
                s[n][2] = (c0     <= tg1) ? s[n][2] * scale : -1e30f;
                s[n][3] = (c0 + 1 <= tg1) ? s[n][3] * scale : -1e30f;
            }
        } else {
#pragma unroll
            for (int n = 0; n < 16; n++)
#pragma unroll
                for (int r = 0; r < 4; r++) s[n][r] *= scale;
        }

        // row max
        float rmax0 = -1e30f, rmax1 = -1e30f;
#pragma unroll
        for (int n = 0; n < 16; n++) {
            rmax0 = fmaxf(rmax0, fmaxf(s[n][0], s[n][1]));
            rmax1 = fmaxf(rmax1, fmaxf(s[n][2], s[n][3]));
        }
        rmax0 = fmaxf(rmax0, __shfl_xor_sync(0xffffffffu, rmax0, 1));
        rmax0 = fmaxf(rmax0, __shfl_xor_sync(0xffffffffu, rmax0, 2));
        rmax1 = fmaxf(rmax1, __shfl_xor_sync(0xffffffffu, rmax1, 1));
        rmax1 = fmaxf(rmax1, __shfl_xor_sync(0xffffffffu, rmax1, 2));

        float mn0 = fmaxf(m_i[0], rmax0);
        float mn1 = fmaxf(m_i[1], rmax1);
        float al0 = __expf(m_i[0] - mn0);
        float al1 = __expf(m_i[1] - mn1);
        m_i[0] = mn0; m_i[1] = mn1;

        float rs0 = 0.f, rs1 = 0.f;
#pragma unroll
        for (int n = 0; n < 16; n++) {
            s[n][0] = __expf(s[n][0] - mn0);
            s[n][1] = __expf(s[n][1] - mn0);
            s[n][2] = __expf(s[n][2] - mn1);
            s[n][3] = __expf(s[n][3] - mn1);
            rs0 += s[n][0] + s[n][1];
            rs1 += s[n][2] + s[n][3];
        }
        rs0 += __shfl_xor_sync(0xffffffffu, rs0, 1);
        rs0 += __shfl_xor_sync(0xffffffffu, rs0, 2);
        rs1 += __shfl_xor_sync(0xffffffffu, rs1, 1);
        rs1 += __shfl_xor_sync(0xffffffffu, rs1, 2);
        l_i[0] = l_i[0] * al0 + rs0;
        l_i[1] = l_i[1] * al1 + rs1;

#pragma unroll
        for (int n = 0; n < 16; n++) {
            o[n][0] *= al0; o[n][1] *= al0;
            o[n][2] *= al1; o[n][3] *= al1;
        }

        // write P to smem
#pragma unroll
        for (int n = 0; n < 16; n++) {
            *(float2*)&Ps[row0 * FP + n * 8 + lc * 2]       = make_float2(s[n][0], s[n][1]);
            *(float2*)&Ps[(row0 + 8) * FP + n * 8 + lc * 2] = make_float2(s[n][2], s[n][3]);
        }
        __syncthreads();   // P visible, K reads done -> reuse buffer for V

        for (int i = tid; i < 128 * 32; i += 256) {
            int r = i >> 5, c4 = (i & 31) * 4;
            float4 val = *(const float4*)&v[((long)(j * 128 + r) * KVH_ + kvh) * HD_ + c4];
            *(float4*)&KVs[r * FP + c4] = val;
        }
        __syncthreads();

        // O += P @ V
#pragma unroll
        for (int kk = 0; kk < 128; kk += 8) {
            unsigned a0 = f2tf(Ps[row0 * FP + kk + lc]);
            unsigned a1 = f2tf(Ps[(row0 + 8) * FP + kk + lc]);
            unsigned a2 = f2tf(Ps[row0 * FP + kk + lc + 4]);
            unsigned a3 = f2tf(Ps[(row0 + 8) * FP + kk + lc + 4]);
#pragma unroll
            for (int n = 0; n < 16; n++) {
                unsigned b0 = f2tf(KVs[(kk + lc) * FP + n * 8 + lr]);
                unsigned b1 = f2tf(KVs[(kk + lc + 4) * FP + n * 8 + lr]);
                mma_tf32(o[n], a0, a1, a2, a3, b0, b1);
            }
        }
    }

    float inv0 = 1.f / l_i[0];
    float inv1 = 1.f / l_i[1];
#pragma unroll
    for (int n = 0; n < 16; n++) {
        int c = n * 8 + lc * 2;
        *(float2*)&attn[((long)tg0 * H_ + h) * HD_ + c] =
            make_float2(o[n][0] * inv0, o[n][1] * inv0);
        *(float2*)&attn[((long)tg1 * H_ + h) * HD_ + c] =
            make_float2(o[n][2] * inv1, o[n][3] * inv1);
    }
}

// ---------------- small fused kernels (float4 vectorized) ----------------
__global__ void rmsnorm_kernel(const float* __restrict__ x, const float* __restrict__ w,
                               float* __restrict__ out, int* __restrict__ cnt)
{
    int t = blockIdx.x, tid = threadIdx.x;
    if (t == 0 && tid < E_) cnt[tid] = 0;
    __shared__ float red[256];
    const float4* row = (const float4*)(x + (long)t * D_);
    float4 v0 = row[tid], v1 = row[tid + 256];
    float s = v0.x * v0.x + v0.y * v0.y + v0.z * v0.z + v0.w * v0.w
            + v1.x * v1.x + v1.y * v1.y + v1.z * v1.z + v1.w * v1.w;
    red[tid] = s; __syncthreads();
    for (int o = 128; o > 0; o >>= 1) { if (tid < o) red[tid] += red[tid + o]; __syncthreads(); }
    float inv = rsqrtf(red[0] / (float)D_ + 1e-6f);
    const float4* wr = (const float4*)w;
    float4 w0 = wr[tid], w1 = wr[tid + 256];
    float4* orow = (float4*)(out + (long)t * D_);
    orow[tid]       = make_float4(v0.x * inv * w0.x, v0.y * inv * w0.y,
                                  v0.z * inv * w0.z, v0.w * inv * w0.w);
    orow[tid + 256] = make_float4(v1.x * inv * w1.x, v1.y * inv * w1.y,
                                  v1.z * inv * w1.z, v1.w * inv * w1.w);
}

__global__ void add_rms_kernel(const float* __restrict__ hid, const float* __restrict__ ao,
                               const float* __restrict__ w,
                               float* __restrict__ h1, float* __restrict__ xn2)
{
    int t = blockIdx.x, tid = threadIdx.x;
    __shared__ float red[256];
    const float4* hr = (const float4*)(hid + (long)t * D_);
    const float4* ar = (const float4*)(ao + (long)t * D_);
    float4 a0 = hr[tid], a1 = hr[tid + 256];
    float4 b0 = ar[tid], b1 = ar[tid + 256];
    float4 v0 = make_float4(a0.x + b0.x, a0.y + b0.y, a0.z + b0.z, a0.w + b0.w);
    float4 v1 = make_float4(a1.x + b1.x, a1.y + b1.y, a1.z + b1.z, a1.w + b1.w);
    float4* h1r = (float4*)(h1 + (long)t * D_);
    h1r[tid] = v0; h1r[tid + 256] = v1;
    float s = v0.x * v0.x + v0.y * v0.y + v0.z * v0.z + v0.w * v0.w
            + v1.x * v1.x + v1.y * v1.y + v1.z * v1.z + v1.w * v1.w;
    red[tid] = s; __syncthreads();
    for (int o = 128; o > 0; o >>= 1) { if (tid < o) red[tid] += red[tid + o]; __syncthreads(); }
    float inv = rsqrtf(red[0] / (float)D_ + 1e-6f);
    const float4* wr = (const float4*)w;
    float4 w0 = wr[tid], w1 = wr[tid + 256];
    float4* xr = (float4*)(xn2 + (long)t * D_);
    xr[tid]       = make_float4(v0.x * inv * w0.x, v0.y * inv * w0.y,
                                v0.z * inv * w0.z, v0.w * inv * w0.w);
    xr[tid + 256] = make_float4(v1.x * inv * w1.x, v1.y * inv * w1.y,
                                v1.z * inv * w1.z, v1.w * inv * w1.w);
}

// one launch for both q and k rope
__global__ void rope_kernel(float* __restrict__ q, float* __restrict__ kk,
                            const int* __restrict__ pos)
{
    int i = blockIdx.x * blockDim.x + threadIdx.x;
    const int totq = T_ * H_ * 64;
    float* x; int nh;
    if (i < totq) { x = q; nh = H_; }
    else {
        i -= totq;
        if (i >= T_ * KVH_ * 64) return;
        x = kk; nh = KVH_;
    }
    int d = i & 63;
    int rest = i >> 6;
    int h = rest % nh;
    int t = rest / nh;
    float inv = exp2f(-(float)d * 0.31143075895f);  // theta^(-d/64)
    float fr = (float)pos[t] * inv;
    float s, c;
    sincosf(fr, &s, &c);
    long base = ((long)t * nh + h) * HD_;
    float x1 = x[base + d], x2 = x[base + 64 + d];
    x[base + d]      = x1 * c - x2 * s;
    x[base + 64 + d] = x2 * c + x1 * s;
}

__global__ void router_kernel(const float* __restrict__ x, const float* __restrict__ gw,
                              int* __restrict__ cnt, int* __restrict__ idx,
                              int* __restrict__ slot, float* __restrict__ wt)
{
    int t = blockIdx.x, tid = threadIdx.x;
    __shared__ float red[256];
    __shared__ float sl[E_];
    float l[E_];
#pragma unroll
    for (int e = 0; e < E_; e++) l[e] = 0.f;
    const float* row = x + (long)t * D_;
    for (int d = tid; d < D_; d += 256) {
        float xv = row[d];
#pragma unroll
        for (int e = 0; e < E_; e++) l[e] += xv * gw[d * E_ + e];
    }
    for (int e = 0; e < E_; e++) {
        red[tid] = l[e]; __syncthreads();
        for (int o = 128; o > 0; o >>= 1) { if (tid < o) red[tid] += red[tid + o]; __syncthreads(); }
        if (tid == 0) sl[e] = red[0];
        __syncthreads();
    }
    if (tid == 0) {
        float mx = sl[0];
        for (int e = 1; e < E_; e++) mx = fmaxf(mx, sl[e]);
        float p[E_]; float s = 0.f;
        for (int e = 0; e < E_; e++) { p[e] = expf(sl[e] - mx); s += p[e]; }
        for (int e = 0; e < E_; e++) p[e] /= s;
        int e0 = 0;
        for (int e = 1; e < E_; e++) if (p[e] > p[e0]) e0 = e;
        int e1 = -1;
        for (int e = 0; e < E_; e++) { if (e == e0) continue; if (e1 < 0 || p[e] > p[e1]) e1 = e; }
        float w0 = p[e0], w1 = p[e1], ws = w0 + w1;
        w0 /= ws; w1 /= ws;
        int p0 = atomicAdd(&cnt[e0], 1);
        idx[e0 * T_ + p0] = t; slot[2 * t] = e0 * T_ + p0; wt[2 * t] = w0;
        int p1 = atomicAdd(&cnt[e1], 1);
        idx[e1 * T_ + p1] = t; slot[2 * t + 1] = e1 * T_ + p1; wt[2 * t + 1] = w1;
    }
}

__global__ void combine_kernel(const float* __restrict__ h1, const float* __restrict__ y,
                               const int* __restrict__ slot, const float* __restrict__ wt,
                               float* __restrict__ out)
{
    int t = blockIdx.x, tid = threadIdx.x;
    long s0 = slot[2 * t], s1 = slot[2 * t + 1];
    float w0 = wt[2 * t], w1 = wt[2 * t + 1];
    const float4* hr = (const float4*)(h1 + (long)t * D_);
    const float4* y0 = (const float4*)(y + s0 * D_);
    const float4* y1 = (const float4*)(y + s1 * D_);
    float4* orow = (float4*)(out + (long)t * D_);
#pragma unroll
    for (int it = 0; it < 2; it++) {
        int d = tid + it * 256;
        float4 hv = hr[d], a = y0[d], b = y1[d];
        orow[d] = make_float4(hv.x + w0 * a.x + w1 * b.x,
                              hv.y + w0 * a.y + w1 * b.y,
                              hv.z + w0 * a.z + w1 * b.z,
                              hv.w + w0 * a.w + w1 * b.w);
    }
}

// ---------------- launch ----------------
extern "C" void kernel_launch(void* const* d_in, const int* in_sizes, int n_in,
                              void* d_out, int out_size)
{
    const float* hidden = (const float*)d_in[0];
    const int*   pos    = (const int*)  d_in[1];
    const float* ln1    = (const float*)d_in[2];
    const float* ln2    = (const float*)d_in[3];
    const float* wq     = (const float*)d_in[4];
    const float* bq     = (const float*)d_in[5];
    const float* wk     = (const float*)d_in[6];
    const float* bk     = (const float*)d_in[7];
    const float* wv     = (const float*)d_in[8];
    const float* bv     = (const float*)d_in[9];
    const float* wo     = (const float*)d_in[10];
    const float* gatew  = (const float*)d_in[11];
    const float* wgate  = (const float*)d_in[12];
    const float* wup    = (const float*)d_in[13];
    const float* wdown  = (const float*)d_in[14];
    float* out = (float*)d_out;

    float *xn, *q, *k, *v, *attn, *h1, *xn2, *gg, *yy, *wt;
    int *cnt, *idx, *slot;
    cudaGetSymbolAddress((void**)&xn,   g_xn);
    cudaGetSymbolAddress((void**)&q,    g_q);
    cudaGetSymbolAddress((void**)&k,    g_k);
    cudaGetSymbolAddress((void**)&v,    g_v);
    cudaGetSymbolAddress((void**)&attn, g_attn);
    cudaGetSymbolAddress((void**)&h1,   g_h1);
    cudaGetSymbolAddress((void**)&xn2,  g_xn2);
    cudaGetSymbolAddress((void**)&gg,   g_g);
    cudaGetSymbolAddress((void**)&yy,   g_y);
    cudaGetSymbolAddress((void**)&cnt,  g_cnt);
    cudaGetSymbolAddress((void**)&idx,  g_idx);
    cudaGetSymbolAddress((void**)&slot, g_slot);
    cudaGetSymbolAddress((void**)&wt,   g_wt);

    static int fa_attr_set = 0;
    if (!fa_attr_set) {
        cudaFuncSetAttribute(flash_attn_kernel,
                             cudaFuncAttributeMaxDynamicSharedMemorySize, FA_SMEM);
        fa_attr_set = 1;
    }

    QKVParams dummy = {};
    dim3 blk(256);

    // x = rmsnorm(hidden) * ln1  (also zeroes cnt)
    rmsnorm_kernel<<<T_, 256>>>(hidden, ln1, xn, cnt);

    // fused QKV projection (+bias): one launch, z selects segment
    QKVParams qkv;
    qkv.B0 = wq; qkv.B1 = wk; qkv.B2 = wv;
    qkv.bias0 = bq; qkv.bias1 = bk; qkv.bias2 = bv;
    qkv.C0 = q; qkv.C1 = k; qkv.C2 = v;
    qkv.N0 = H_ * HD_; qkv.N1 = KVH_ * HD_; qkv.N2 = KVH_ * HD_;
    gemm_kernel<false, true, false><<<dim3(16, 16, 3), blk>>>(
        xn, D_, 0, nullptr, 0, 0, nullptr, nullptr, 0, 0,
        T_, 0, D_, nullptr, nullptr, qkv);

    // RoPE (q and k in one launch)
    rope_kernel<<<(T_ * (H_ + KVH_) * 64 + 255) / 256, 256>>>(q, k, pos);

    // flash attention (fused QK^T + softmax + PV, causal)
    flash_attn_kernel<<<dim3(16, 16), 256, FA_SMEM>>>(q, k, v, attn);

    // O projection -> xn (scratch reuse)
    gemm_kernel<false, false, false><<<dim3(16, 16, 1), blk>>>(
        attn, H_ * HD_, 0, wo, D_, 0, nullptr, xn, D_, 0,
        T_, D_, H_ * HD_, nullptr, nullptr, dummy);

    // h1 = hidden + attn_out ; xn2 = rmsnorm(h1) * ln2
    add_rms_kernel<<<T_, 256>>>(hidden, xn, ln2, h1, xn2);

    // router: top-2 experts per token
    router_kernel<<<T_, 256>>>(xn2, gatew, cnt, idx, slot, wt);

    // gate proj (gathered)
    gemm_kernel<true, false, false><<<dim3(8, 16, E_), blk>>>(
        xn2, D_, 0, wgate, I_, (long)D_ * I_, nullptr, gg, I_, (long)T_ * I_,
        T_, I_, D_, cnt, idx, dummy);

    // up proj (gathered) with fused ff = silu(g) * u written into gg
    gemm_kernel<true, false, true><<<dim3(8, 16, E_), blk>>>(
        xn2, D_, 0, wup, I_, (long)D_ * I_, nullptr, gg, I_, (long)T_ * I_,
        T_, I_, D_, cnt, idx, dummy);

    // y_e = ff_e @ Wd[e]
    gemm_kernel<false, false, false><<<dim3(16, 16, E_), blk>>>(
        gg, I_, (long)T_ * I_, wdown, D_, (long)I_ * D_, nullptr, yy, D_, (long)T_ * D_,
        T_, D_, I_, cnt, nullptr, dummy);

    // out = h1 + w0*y[slot0] + w1*y[slot1]
    combine_kernel<<<T_, 256>>>(h1, yy, slot, wt, out);
}

// round 8
// speedup vs baseline: 1.0220x; 1.0220x over previous
#include <cuda_runtime.h>
#include <math.h>

#define T_ 2048
#define D_ 2048
#define H_ 16
#define KVH_ 4
#define HD_ 128
#define E_ 8
#define I_ 1024
#define TOPK_ 2

// ---------------- static scratch (no allocations allowed) ----------------
__device__ float g_xn  [(size_t)T_ * D_];
__device__ float g_q   [(size_t)T_ * H_ * HD_];
__device__ float g_k   [(size_t)T_ * KVH_ * HD_];
__device__ float g_v   [(size_t)T_ * KVH_ * HD_];
__device__ float g_attn[(size_t)T_ * H_ * HD_];
__device__ float g_h1  [(size_t)T_ * D_];
__device__ float g_xn2 [(size_t)T_ * D_];
__device__ float g_g   [(size_t)E_ * T_ * I_];
__device__ float g_y   [(size_t)E_ * T_ * D_];
__device__ int   g_cnt [E_];
__device__ int   g_idx [E_ * T_];
__device__ int   g_slot[T_ * TOPK_];
__device__ float g_wt  [T_ * TOPK_];

struct QKVParams {
    const float* B0; const float* B1; const float* B2;
    const float* bias0; const float* bias1; const float* bias2;
    float* C0; float* C1; float* C2;
    int N0, N1, N2;
};

// ---------------- tf32 mma helpers ----------------
__device__ __forceinline__ unsigned f2tf(float f) {
    unsigned r;
    asm("cvt.rna.tf32.f32 %0, %1;" : "=r"(r) : "f"(f));
    return r;
}

__device__ __forceinline__ void mma_tf32(float c[4],
                                         unsigned a0, unsigned a1, unsigned a2, unsigned a3,
                                         unsigned b0, unsigned b1)
{
    asm volatile("mma.sync.aligned.m16n8k8.row.col.f32.tf32.tf32.f32 "
                 "{%0,%1,%2,%3}, {%4,%5,%6,%7}, {%8,%9}, {%0,%1,%2,%3};"
                 : "+f"(c[0]), "+f"(c[1]), "+f"(c[2]), "+f"(c[3])
                 : "r"(a0), "r"(a1), "r"(a2), "r"(a3), "r"(b0), "r"(b1));
}

__device__ __forceinline__ void cp16(unsigned dst, const void* src, bool pred) {
    int sz = pred ? 16 : 0;
    asm volatile("cp.async.cg.shared.global [%0], [%1], 16, %2;"
                 :: "r"(dst), "l"(src), "r"(sz));
}
__device__ __forceinline__ void cp_commit() { asm volatile("cp.async.commit_group;"); }
template<int N>
__device__ __forceinline__ void cp_wait() { asm volatile("cp.async.wait_group %0;" :: "n"(N)); }

// ---------------- tf32 tensor-core GEMM: 128x128x16, 256 thr (R3 known-good) ----------------
// C[m,n] = sum_k A[m,k] * B[k,n]   (B row-major K x N)
// GATHER: A rows indexed via gidx[z*T_ + m]
// MULTI:  z in {0,1,2} selects (B, bias, C, N) from mp; ldb=ldc=N
// SILU:   epilogue: C[m,n] = silu(C[m,n]) * acc   (read-modify-write)
#define A_PITCH 20      // 16 k + 4 pad
#define B_PITCH 136     // 128 n + 8 pad
#define ABUF (128 * A_PITCH)
#define BBUF (16 * B_PITCH)

template<bool GATHER, bool MULTI, bool SILU>
__global__ __launch_bounds__(256)
void gemm_kernel(const float* __restrict__ A, int lda, long sA,
                 const float* __restrict__ B, int ldb, long sB,
                 const float* __restrict__ bias,
                 float* __restrict__ C, int ldc, long sC,
                 int M, int N, int Kd,
                 const int* __restrict__ cnt, const int* __restrict__ gidx,
                 QKVParams mp)
{
    int z = blockIdx.z;
    if (MULTI) {
        if (z == 0)      { B = mp.B0; bias = mp.bias0; C = mp.C0; N = mp.N0; }
        else if (z == 1) { B = mp.B1; bias = mp.bias1; C = mp.C1; N = mp.N1; }
        else             { B = mp.B2; bias = mp.bias2; C = mp.C2; N = mp.N2; }
        ldb = N; ldc = N;
    } else {
        A += (long)z * sA;
        B += (long)z * sB;
        C += (long)z * sC;
        if (cnt) M = cnt[z];
    }
    const int* rows = GATHER ? (gidx + z * T_) : nullptr;

    int m0 = blockIdx.y * 128;
    int n0 = blockIdx.x * 128;
    if (m0 >= M || n0 >= N) return;

    __shared__ float As[2][ABUF];
    __shared__ float Bs[2][BBUF];

    int tid = threadIdx.x;
    int qa0 = tid, qa1 = tid + 256;

    int aM0 = qa0 >> 2, aK0 = (qa0 & 3) * 4;
    int aM1 = qa1 >> 2, aK1 = (qa1 & 3) * 4;
    bool aok0 = (m0 + aM0) < M;
    bool aok1 = (m0 + aM1) < M;
    long arow0 = 0, arow1 = 0;
    if (aok0) arow0 = GATHER ? (long)rows[m0 + aM0] : (long)(m0 + aM0);
    if (aok1) arow1 = GATHER ? (long)rows[m0 + aM1] : (long)(m0 + aM1);

    int bR0 = qa0 >> 5, bC0 = (qa0 & 31) * 4;
    int bR1 = qa1 >> 5, bC1 = (qa1 & 31) * 4;

    unsigned asb = (unsigned)__cvta_generic_to_shared(&As[0][0]);
    unsigned bsb = (unsigned)__cvta_generic_to_shared(&Bs[0][0]);
    unsigned adst0 = asb + (aM0 * A_PITCH + aK0) * 4;
    unsigned adst1 = asb + (aM1 * A_PITCH + aK1) * 4;
    unsigned bdst0 = bsb + (bR0 * B_PITCH + bC0) * 4;
    unsigned bdst1 = bsb + (bR1 * B_PITCH + bC1) * 4;

    float acc[4][4][4];
#pragma unroll
    for (int i = 0; i < 4; i++)
#pragma unroll
        for (int j = 0; j < 4; j++)
#pragma unroll
            for (int r = 0; r < 4; r++) acc[i][j][r] = 0.f;

    int wid = tid >> 5, lane = tid & 31;
    int lr = lane >> 2, lc = lane & 3;
    int wm = (wid & 1) * 64;
    int wn = (wid >> 1) * 32;

    const int KT = Kd >> 4;

    {
        cp16(adst0, A + arow0 * lda + aK0, aok0);
        cp16(adst1, A + arow1 * lda + aK1, aok1);
        cp16(bdst0, B + (long)bR0 * ldb + n0 + bC0, true);
        cp16(bdst1, B + (long)bR1 * ldb + n0 + bC1, true);
        cp_commit();
    }

    for (int kt = 0; kt < KT; kt++) {
        if (kt + 1 < KT) {
            int k0 = (kt + 1) << 4;
            unsigned off_a = ((kt + 1) & 1) * ABUF * 4;
            unsigned off_b = ((kt + 1) & 1) * BBUF * 4;
            cp16(adst0 + off_a, A + arow0 * lda + k0 + aK0, aok0);
            cp16(adst1 + off_a, A + arow1 * lda + k0 + aK1, aok1);
            cp16(bdst0 + off_b, B + (long)(k0 + bR0) * ldb + n0 + bC0, true);
            cp16(bdst1 + off_b, B + (long)(k0 + bR1) * ldb + n0 + bC1, true);
            cp_commit();
            cp_wait<1>();
        } else {
            cp_wait<0>();
        }
        __syncthreads();

        int buf = kt & 1;
        const float* Ab = As[buf];
        const float* Bb = Bs[buf];

#pragma unroll
        for (int kk = 0; kk < 16; kk += 8) {
            unsigned afr[4][4];
#pragma unroll
            for (int i = 0; i < 4; i++) {
                int mb = wm + i * 16;
                afr[i][0] = f2tf(Ab[(mb + lr)     * A_PITCH + kk + lc]);
                afr[i][1] = f2tf(Ab[(mb + lr + 8) * A_PITCH + kk + lc]);
                afr[i][2] = f2tf(Ab[(mb + lr)     * A_PITCH + kk + lc + 4]);
                afr[i][3] = f2tf(Ab[(mb + lr + 8) * A_PITCH + kk + lc + 4]);
            }
            unsigned bfr[4][2];
#pragma unroll
            for (int j = 0; j < 4; j++) {
                int nb = wn + j * 8;
                bfr[j][0] = f2tf(Bb[(kk + lc)     * B_PITCH + nb + lr]);
                bfr[j][1] = f2tf(Bb[(kk + lc + 4) * B_PITCH + nb + lr]);
            }
#pragma unroll
            for (int i = 0; i < 4; i++)
#pragma unroll
                for (int j = 0; j < 4; j++)
                    mma_tf32(acc[i][j], afr[i][0], afr[i][1], afr[i][2], afr[i][3],
                             bfr[j][0], bfr[j][1]);
        }
        __syncthreads();
    }

    // epilogue
#pragma unroll
    for (int i = 0; i < 4; i++) {
#pragma unroll
        for (int j = 0; j < 4; j++) {
            int m = m0 + wm + i * 16 + lr;
            int n = n0 + wn + j * 8 + lc * 2;
            float bv0 = 0.f, bv1 = 0.f;
            if (bias) { bv0 = bias[n]; bv1 = bias[n + 1]; }
            if (m < M) {
                float v0 = acc[i][j][0] + bv0, v1 = acc[i][j][1] + bv1;
                if (SILU) {
                    float2 g = *(float2*)&C[(long)m * ldc + n];
                    v0 = g.x / (1.f + __expf(-g.x)) * v0;
                    v1 = g.y / (1.f + __expf(-g.y)) * v1;
                }
                *(float2*)&C[(long)m * ldc + n] = make_float2(v0, v1);
            }
            if (m + 8 < M) {
                float v0 = acc[i][j][2] + bv0, v1 = acc[i][j][3] + bv1;
                if (SILU) {
                    float2 g = *(float2*)&C[(long)(m + 8) * ldc + n];
                    v0 = g.x / (1.f + __expf(-g.x)) * v0;
                    v1 = g.y / (1.f + __expf(-g.y)) * v1;
                }
                *(float2*)&C[(long)(m + 8) * ldc + n] = make_float2(v0, v1);
            }
        }
    }
}

// ---------------- flash attention (tf32 mma, online softmax) ----------------
// R3 structure, but smem tiles hold PRE-CONVERTED tf32 bit patterns:
// cvt.rna applied once at fill time, inner loops are pure LDS -> MMA.
// Numerically identical to R3 (same rna conversion per value, same MMA order).
// Grid (16 qblocks, 16 heads), 256 thr (8 warps). Warp owns 16 rows x 128 cols.
#define FP 132
#define FA_SMEM (3 * 128 * FP * 4)

__global__ __launch_bounds__(256)
void flash_attn_kernel(const float* __restrict__ q, const float* __restrict__ k,
                       const float* __restrict__ v, float* __restrict__ attn)
{
    int qi = blockIdx.x;
    int h  = blockIdx.y;
    int kvh = h >> 2;
    extern __shared__ unsigned smu[];
    unsigned* Qs  = smu;
    unsigned* KVs = smu + 128 * FP;
    unsigned* Ps  = smu + 2 * 128 * FP;

    int tid = threadIdx.x, wid = tid >> 5, lane = tid & 31;
    int lr = lane >> 2, lc = lane & 3;
    const float scale = 0.08838834764831845f;

    // load Q tile (convert to tf32 bits once)
    for (int i = tid; i < 128 * 32; i += 256) {
        int r = i >> 5, c4 = (i & 31) * 4;
        float4 val = *(const float4*)&q[((long)(qi * 128 + r) * H_ + h) * HD_ + c4];
        uint4 b = make_uint4(f2tf(val.x), f2tf(val.y), f2tf(val.z), f2tf(val.w));
        *(uint4*)&Qs[r * FP + c4] = b;
    }

    float m_i[2] = {-1e30f, -1e30f};
    float l_i[2] = {0.f, 0.f};
    float o[16][4];
#pragma unroll
    for (int n = 0; n < 16; n++)
#pragma unroll
        for (int r = 0; r < 4; r++) o[n][r] = 0.f;

    int row0 = wid * 16 + lr;        // local rows: row0, row0+8
    int tg0 = qi * 128 + row0;
    int tg1 = tg0 + 8;

    for (int j = 0; j <= qi; j++) {
        __syncthreads();   // prior iter's V reads done (and Q stores on first iter)
        for (int i = tid; i < 128 * 32; i += 256) {
            int r = i >> 5, c4 = (i & 31) * 4;
            float4 val = *(const float4*)&k[((long)(j * 128 + r) * KVH_ + kvh) * HD_ + c4];
            uint4 b = make_uint4(f2tf(val.x), f2tf(val.y), f2tf(val.z), f2tf(val.w));
            *(uint4*)&KVs[r * FP + c4] = b;
        }
        __syncthreads();

        // S = Q @ K^T  (pure LDS -> MMA, no conversions)
        float s[16][4];
#pragma unroll
        for (int n = 0; n < 16; n++)
#pragma unroll
            for (int r = 0; r < 4; r++) s[n][r] = 0.f;

#pragma unroll
        for (int kk = 0; kk < 128; kk += 8) {
            unsigned a0 = Qs[row0 * FP + kk + lc];
            unsigned a1 = Qs[(row0 + 8) * FP + kk + lc];
            unsigned a2 = Qs[row0 * FP + kk + lc + 4];
            unsigned a3 = Qs[(row0 + 8) * FP + kk + lc + 4];
#pragma unroll
            for (int n = 0; n < 16; n++) {
                unsigned b0 = KVs[(n * 8 + lr) * FP + kk + lc];
                unsigned b1 = KVs[(n * 8 + lr) * FP + kk + lc + 4];
                mma_tf32(s[n], a0, a1, a2, a3, b0, b1);
            }
        }

        // scale + causal mask (only diagonal block needs mask)
        if (j == qi) {
#pragma unroll
            for (int n = 0; n < 16; n++) {
                int c0 = j * 128 + n * 8 + lc * 2;
                s[n][0] = (c0     <= tg0) ? s[n][0] * scale : -1e30f;
                s[n][1] = (c0 + 1 <= tg0) ? s[n][1] * scale : -1e30f;
                s[n][2] = (c0     <= tg1) ? s[n][2] * scale : -1e30f;
                s[n][3] = (c0 + 1 <= tg1) ? s[n][3] * scale : -1e30f;
            }
        } else {
#pragma unroll
            for (int n = 0; n < 16; n++)
#pragma unroll
                for (int r = 0; r < 4; r++) s[n][r] *= scale;
        }

        // row max
        float rmax0 = -1e30f, rmax1 = -1e30f;
#pragma unroll
        for (int n = 0; n < 16; n++) {
            rmax0 = fmaxf(rmax0, fmaxf(s[n][0], s[n][1]));
            rmax1 = fmaxf(rmax1, fmaxf(s[n][2], s[n][3]));
        }
        rmax0 = fmaxf(rmax0, __shfl_xor_sync(0xffffffffu, rmax0, 1));
        rmax0 = fmaxf(rmax0, __shfl_xor_sync(0xffffffffu, rmax0, 2));
        rmax1 = fmaxf(rmax1, __shfl_xor_sync(0xffffffffu, rmax1, 1));
        rmax1 = fmaxf(rmax1, __shfl_xor_sync(0xffffffffu, rmax1, 2));

        float mn0 = fmaxf(m_i[0], rmax0);
        float mn1 = fmaxf(m_i[1], rmax1);
        float al0 = __expf(m_i[0] - mn0);
        float al1 = __expf(m_i[1] - mn1);
        m_i[0] = mn0; m_i[1] = mn1;

        float rs0 = 0.f, rs1 = 0.f;
#pragma unroll
        for (int n = 0; n < 16; n++) {
            s[n][0] = __expf(s[n][0] - mn0);
            s[n][1] = __expf(s[n][1] - mn0);
            s[n][2] = __expf(s[n][2] - mn1);
            s[n][3] = __expf(s[n][3] - mn1);
            rs0 += s[n][0] + s[n][1];
            rs1 += s[n][2] + s[n][3];
        }
        rs0 += __shfl_xor_sync(0xffffffffu, rs0, 1);
        rs0 += __shfl_xor_sync(0xffffffffu, rs0, 2);
        rs1 += __shfl_xor_sync(0xffffffffu, rs1, 1);
        rs1 += __shfl_xor_sync(0xffffffffu, rs1, 2);
        l_i[0] = l_i[0] * al0 + rs0;
        l_i[1] = l_i[1] * al1 + rs1;

#pragma unroll
        for (int n = 0; n < 16; n++) {
            o[n][0] *= al0; o[n][1] *= al0;
            o[n][2] *= al1; o[n][3] *= al1;
        }

        // write P to smem (convert to tf32 bits at store)
#pragma unroll
        for (int n = 0; n < 16; n++) {
            *(uint2*)&Ps[row0 * FP + n * 8 + lc * 2] =
                make_uint2(f2tf(s[n][0]), f2tf(s[n][1]));
            *(uint2*)&Ps[(row0 + 8) * FP + n * 8 + lc * 2] =
                make_uint2(f2tf(s[n][2]), f2tf(s[n][3]));
        }
        __syncthreads();   // P visible, K reads done -> reuse buffer for V

        for (int i = tid; i < 128 * 32; i += 256) {
            int r = i >> 5, c4 = (i & 31) * 4;
            float4 val = *(const float4*)&v[((long)(j * 128 + r) * KVH_ + kvh) * HD_ + c4];
            uint4 b = make_uint4(f2tf(val.x), f2tf(val.y), f2tf(val.z), f2tf(val.w));
            *(uint4*)&KVs[r * FP + c4] = b;
        }
        __syncthreads();

        // O += P @ V  (pure LDS -> MMA)
#pragma unroll
        for (int kk = 0; kk < 128; kk += 8) {
            unsigned a0 = Ps[row0 * FP + kk + lc];
            unsigned a1 = Ps[(row0 + 8) * FP + kk + lc];
            unsigned a2 = Ps[row0 * FP + kk + lc + 4];
            unsigned a3 = Ps[(row0 + 8) * FP + kk + lc + 4];
#pragma unroll
            for (int n = 0; n < 16; n++) {
                unsigned b0 = KVs[(kk + lc) * FP + n * 8 + lr];
                unsigned b1 = KVs[(kk + lc + 4) * FP + n * 8 + lr];
                mma_tf32(o[n], a0, a1, a2, a3, b0, b1);
            }
        }
    }

    float inv0 = 1.f / l_i[0];
    float inv1 = 1.f / l_i[1];
#pragma unroll
    for (int n = 0; n < 16; n++) {
        int c = n * 8 + lc * 2;
        *(float2*)&attn[((long)tg0 * H_ + h) * HD_ + c] =
            make_float2(o[n][0] * inv0, o[n][1] * inv0);
        *(float2*)&attn[((long)tg1 * H_ + h) * HD_ + c] =
            make_float2(o[n][2] * inv1, o[n][3] * inv1);
    }
}

// ---------------- small fused kernels (float4 vectorized) ----------------
__global__ void rmsnorm_kernel(const float* __restrict__ x, const float* __restrict__ w,
                               float* __restrict__ out, int* __restrict__ cnt)
{
    int t = blockIdx.x, tid = threadIdx.x;
    if (t == 0 && tid < E_) cnt[tid] = 0;
    __shared__ float red[256];
    const float4* row = (const float4*)(x + (long)t * D_);
    float4 v0 = row[tid], v1 = row[tid + 256];
    float s = v0.x * v0.x + v0.y * v0.y + v0.z * v0.z + v0.w * v0.w
            + v1.x * v1.x + v1.y * v1.y + v1.z * v1.z + v1.w * v1.w;
    red[tid] = s; __syncthreads();
    for (int o = 128; o > 0; o >>= 1) { if (tid < o) red[tid] += red[tid + o]; __syncthreads(); }
    float inv = rsqrtf(red[0] / (float)D_ + 1e-6f);
    const float4* wr = (const float4*)w;
    float4 w0 = wr[tid], w1 = wr[tid + 256];
    float4* orow = (float4*)(out + (long)t * D_);
    orow[tid]       = make_float4(v0.x * inv * w0.x, v0.y * inv * w0.y,
                                  v0.z * inv * w0.z, v0.w * inv * w0.w);
    orow[tid + 256] = make_float4(v1.x * inv * w1.x, v1.y * inv * w1.y,
                                  v1.z * inv * w1.z, v1.w * inv * w1.w);
}

__global__ void add_rms_kernel(const float* __restrict__ hid, const float* __restrict__ ao,
                               const float* __restrict__ w,
                               float* __restrict__ h1, float* __restrict__ xn2)
{
    int t = blockIdx.x, tid = threadIdx.x;
    __shared__ float red[256];
    const float4* hr = (const float4*)(hid + (long)t * D_);
    const float4* ar = (const float4*)(ao + (long)t * D_);
    float4 a0 = hr[tid], a1 = hr[tid + 256];
    float4 b0 = ar[tid], b1 = ar[tid + 256];
    float4 v0 = make_float4(a0.x + b0.x, a0.y + b0.y, a0.z + b0.z, a0.w + b0.w);
    float4 v1 = make_float4(a1.x + b1.x, a1.y + b1.y, a1.z + b1.z, a1.w + b1.w);
    float4* h1r = (float4*)(h1 + (long)t * D_);
    h1r[tid] = v0; h1r[tid + 256] = v1;
    float s = v0.x * v0.x + v0.y * v0.y + v0.z * v0.z + v0.w * v0.w
            + v1.x * v1.x + v1.y * v1.y + v1.z * v1.z + v1.w * v1.w;
    red[tid] = s; __syncthreads();
    for (int o = 128; o > 0; o >>= 1) { if (tid < o) red[tid] += red[tid + o]; __syncthreads(); }
    float inv = rsqrtf(red[0] / (float)D_ + 1e-6f);
    const float4* wr = (const float4*)w;
    float4 w0 = wr[tid], w1 = wr[tid + 256];
    float4* xr = (float4*)(xn2 + (long)t * D_);
    xr[tid]       = make_float4(v0.x * inv * w0.x, v0.y * inv * w0.y,
                                v0.z * inv * w0.z, v0.w * inv * w0.w);
    xr[tid + 256] = make_float4(v1.x * inv * w1.x, v1.y * inv * w1.y,
                                v1.z * inv * w1.z, v1.w * inv * w1.w);
}

// one launch for both q and k rope
__global__ void rope_kernel(float* __restrict__ q, float* __restrict__ kk,
                            const int* __restrict__ pos)
{
    int i = blockIdx.x * blockDim.x + threadIdx.x;
    const int totq = T_ * H_ * 64;
    float* x; int nh;
    if (i < totq) { x = q; nh = H_; }
    else {
        i -= totq;
        if (i >= T_ * KVH_ * 64) return;
        x = kk; nh = KVH_;
    }
    int d = i & 63;
    int rest = i >> 6;
    int h = rest % nh;
    int t = rest / nh;
    float inv = exp2f(-(float)d * 0.31143075895f);  // theta^(-d/64)
    float fr = (float)pos[t] * inv;
    float s, c;
    sincosf(fr, &s, &c);
    long base = ((long)t * nh + h) * HD_;
    float x1 = x[base + d], x2 = x[base + 64 + d];
    x[base + d]      = x1 * c - x2 * s;
    x[base + 64 + d] = x2 * c + x1 * s;
}

__global__ void router_kernel(const float* __restrict__ x, const float* __restrict__ gw,
                              int* __restrict__ cnt, int* __restrict__ idx,
                              int* __restrict__ slot, float* __restrict__ wt)
{
    int t = blockIdx.x, tid = threadIdx.x;
    __shared__ float red[256];
    __shared__ float sl[E_];
    float l[E_];
#pragma unroll
    for (int e = 0; e < E_; e++) l[e] = 0.f;
    const float* row = x + (long)t * D_;
    for (int d = tid; d < D_; d += 256) {
        float xv = row[d];
#pragma unroll
        for (int e = 0; e < E_; e++) l[e] += xv * gw[d * E_ + e];
    }
    for (int e = 0; e < E_; e++) {
        red[tid] = l[e]; __syncthreads();
        for (int o = 128; o > 0; o >>= 1) { if (tid < o) red[tid] += red[tid + o]; __syncthreads(); }
        if (tid == 0) sl[e] = red[0];
        __syncthreads();
    }
    if (tid == 0) {
        float mx = sl[0];
        for (int e = 1; e < E_; e++) mx = fmaxf(mx, sl[e]);
        float p[E_]; float s = 0.f;
        for (int e = 0; e < E_; e++) { p[e] = expf(sl[e] - mx); s += p[e]; }
        for (int e = 0; e < E_; e++) p[e] /= s;
        int e0 = 0;
        for (int e = 1; e < E_; e++) if (p[e] > p[e0]) e0 = e;
        int e1 = -1;
        for (int e = 0; e < E_; e++) { if (e == e0) continue; if (e1 < 0 || p[e] > p[e1]) e1 = e; }
        float w0 = p[e0], w1 = p[e1], ws = w0 + w1;
        w0 /= ws; w1 /= ws;
        int p0 = atomicAdd(&cnt[e0], 1);
        idx[e0 * T_ + p0] = t; slot[2 * t] = e0 * T_ + p0; wt[2 * t] = w0;
        int p1 = atomicAdd(&cnt[e1], 1);
        idx[e1 * T_ + p1] = t; slot[2 * t + 1] = e1 * T_ + p1; wt[2 * t + 1] = w1;
    }
}

__global__ void combine_kernel(const float* __restrict__ h1, const float* __restrict__ y,
                               const int* __restrict__ slot, const float* __restrict__ wt,
                               float* __restrict__ out)
{
    int t = blockIdx.x, tid = threadIdx.x;
    long s0 = slot[2 * t], s1 = slot[2 * t + 1];
    float w0 = wt[2 * t], w1 = wt[2 * t + 1];
    const float4* hr = (const float4*)(h1 + (long)t * D_);
    const float4* y0 = (const float4*)(y + s0 * D_);
    const float4* y1 = (const float4*)(y + s1 * D_);
    float4* orow = (float4*)(out + (long)t * D_);
#pragma unroll
    for (int it = 0; it < 2; it++) {
        int d = tid + it * 256;
        float4 hv = hr[d], a = y0[d], b = y1[d];
        orow[d] = make_float4(hv.x + w0 * a.x + w1 * b.x,
                              hv.y + w0 * a.y + w1 * b.y,
                              hv.z + w0 * a.z + w1 * b.z,
                              hv.w + w0 * a.w + w1 * b.w);
    }
}

// ---------------- launch ----------------
extern "C" void kernel_launch(void* const* d_in, const int* in_sizes, int n_in,
                              void* d_out, int out_size)
{
    const float* hidden = (const float*)d_in[0];
    const int*   pos    = (const int*)  d_in[1];
    const float* ln1    = (const float*)d_in[2];
    const float* ln2    = (const float*)d_in[3];
    const float* wq     = (const float*)d_in[4];
    const float* bq     = (const float*)d_in[5];
    const float* wk     = (const float*)d_in[6];
    const float* bk     = (const float*)d_in[7];
    const float* wv     = (const float*)d_in[8];
    const float* bv     = (const float*)d_in[9];
    const float* wo     = (const float*)d_in[10];
    const float* gatew  = (const float*)d_in[11];
    const float* wgate  = (const float*)d_in[12];
    const float* wup    = (const float*)d_in[13];
    const float* wdown  = (const float*)d_in[14];
    float* out = (float*)d_out;

    float *xn, *q, *k, *v, *attn, *h1, *xn2, *gg, *yy, *wt;
    int *cnt, *idx, *slot;
    cudaGetSymbolAddress((void**)&xn,   g_xn);
    cudaGetSymbolAddress((void**)&q,    g_q);
    cudaGetSymbolAddress((void**)&k,    g_k);
    cudaGetSymbolAddress((void**)&v,    g_v);
    cudaGetSymbolAddress((void**)&attn, g_attn);
    cudaGetSymbolAddress((void**)&h1,   g_h1);
    cudaGetSymbolAddress((void**)&xn2,  g_xn2);
    cudaGetSymbolAddress((void**)&gg,   g_g);
    cudaGetSymbolAddress((void**)&yy,   g_y);
    cudaGetSymbolAddress((void**)&cnt,  g_cnt);
    cudaGetSymbolAddress((void**)&idx,  g_idx);
    cudaGetSymbolAddress((void**)&slot, g_slot);
    cudaGetSymbolAddress((void**)&wt,   g_wt);

    static int fa_attr_set = 0;
    if (!fa_attr_set) {
        cudaFuncSetAttribute(flash_attn_kernel,
                             cudaFuncAttributeMaxDynamicSharedMemorySize, FA_SMEM);
        fa_attr_set = 1;
    }

    QKVParams dummy = {};
    dim3 blk(256);

    // x = rmsnorm(hidden) * ln1  (also zeroes cnt)
    rmsnorm_kernel<<<T_, 256>>>(hidden, ln1, xn, cnt);

    // fused QKV projection (+bias): one launch, z selects segment
    QKVParams qkv;
    qkv.B0 = wq; qkv.B1 = wk; qkv.B2 = wv;
    qkv.bias0 = bq; qkv.bias1 = bk; qkv.bias2 = bv;
    qkv.C0 = q; qkv.C1 = k; qkv.C2 = v;
    qkv.N0 = H_ * HD_; qkv.N1 = KVH_ * HD_; qkv.N2 = KVH_ * HD_;
    gemm_kernel<false, true, false><<<dim3(16, 16, 3), blk>>>(
        xn, D_, 0, nullptr, 0, 0, nullptr, nullptr, 0, 0,
        T_, 0, D_, nullptr, nullptr, qkv);

    // RoPE (q and k in one launch)
    rope_kernel<<<(T_ * (H_ + KVH_) * 64 + 255) / 256, 256>>>(q, k, pos);

    // flash attention (fused QK^T + softmax + PV, causal)
    flash_attn_kernel<<<dim3(16, 16), 256, FA_SMEM>>>(q, k, v, attn);

    // O projection -> xn (scratch reuse)
    gemm_kernel<false, false, false><<<dim3(16, 16, 1), blk>>>(
        attn, H_ * HD_, 0, wo, D_, 0, nullptr, xn, D_, 0,
        T_, D_, H_ * HD_, nullptr, nullptr, dummy);

    // h1 = hidden + attn_out ; xn2 = rmsnorm(h1) * ln2
    add_rms_kernel<<<T_, 256>>>(hidden, xn, ln2, h1, xn2);

    // router: top-2 experts per token
    router_kernel<<<T_, 256>>>(xn2, gatew, cnt, idx, slot, wt);

    // gate proj (gathered)
    gemm_kernel<true, false, false><<<dim3(8, 16, E_), blk>>>(
        xn2, D_, 0, wgate, I_, (long)D_ * I_, nullptr, gg, I_, (long)T_ * I_,
        T_, I_, D_, cnt, idx, dummy);

    // up proj (gathered) with fused ff = silu(g) * u written into gg
    gemm_kernel<true, false, true><<<dim3(8, 16, E_), blk>>>(
        xn2, D_, 0, wup, I_, (long)D_ * I_, nullptr, gg, I_, (long)T_ * I_,
        T_, I_, D_, cnt, idx, dummy);

    // y_e = ff_e @ Wd[e]
    gemm_kernel<false, false, false><<<dim3(16, 16, E_), blk>>>(
        gg, I_, (long)T_ * I_, wdown, D_, (long)I_ * D_, nullptr, yy, D_, (long)T_ * D_,
        T_, D_, I_, cnt, nullptr, dummy);

    // out = h1 + w0*y[slot0] + w1*y[slot1]
    combine_kernel<<<T_, 256>>>(h1, yy, slot, wt, out);
}

// round 10
// speedup vs baseline: 1.5470x; 1.5136x over previous
#include <cuda_runtime.h>
#include <math.h>

#define T_ 2048
#define D_ 2048
#define H_ 16
#define KVH_ 4
#define HD_ 128
#define E_ 8
#define I_ 1024
#define TOPK_ 2

// ---------------- static scratch (no allocations allowed) ----------------
__device__ float g_xn  [(size_t)T_ * D_];
__device__ float g_q   [(size_t)T_ * H_ * HD_];
__device__ float g_k   [(size_t)T_ * KVH_ * HD_];
__device__ float g_v   [(size_t)T_ * KVH_ * HD_];
__device__ float g_attn[(size_t)T_ * H_ * HD_];
__device__ float g_h1  [(size_t)T_ * D_];
__device__ float g_xn2 [(size_t)T_ * D_];
__device__ float g_g   [(size_t)E_ * T_ * I_];
__device__ float g_y   [(size_t)E_ * T_ * D_];
__device__ int   g_cnt [E_];
__device__ int   g_idx [E_ * T_];
__device__ int   g_slot[T_ * TOPK_];
__device__ float g_wt  [T_ * TOPK_];

struct QKVParams {
    const float* B0; const float* B1; const float* B2;
    const float* bias0; const float* bias1; const float* bias2;
    float* C0; float* C1; float* C2;
    int N0, N1, N2;
};

// ---------------- tf32 mma helpers ----------------
__device__ __forceinline__ unsigned f2tf(float f) {
    unsigned r;
    asm("cvt.rna.tf32.f32 %0, %1;" : "=r"(r) : "f"(f));
    return r;
}

__device__ __forceinline__ void mma_tf32(float c[4],
                                         unsigned a0, unsigned a1, unsigned a2, unsigned a3,
                                         unsigned b0, unsigned b1)
{
    asm volatile("mma.sync.aligned.m16n8k8.row.col.f32.tf32.tf32.f32 "
                 "{%0,%1,%2,%3}, {%4,%5,%6,%7}, {%8,%9}, {%0,%1,%2,%3};"
                 : "+f"(c[0]), "+f"(c[1]), "+f"(c[2]), "+f"(c[3])
                 : "r"(a0), "r"(a1), "r"(a2), "r"(a3), "r"(b0), "r"(b1));
}

__device__ __forceinline__ void cp16(unsigned dst, const void* src, bool pred) {
    int sz = pred ? 16 : 0;
    asm volatile("cp.async.cg.shared.global [%0], [%1], 16, %2;"
                 :: "r"(dst), "l"(src), "r"(sz));
}
__device__ __forceinline__ void cp_commit() { asm volatile("cp.async.commit_group;"); }
template<int N>
__device__ __forceinline__ void cp_wait() { asm volatile("cp.async.wait_group %0;" :: "n"(N)); }

// ---------------- tf32 tensor-core GEMM: 128x128x16, 256 thr (R3 known-good) ----------------
// C[m,n] = sum_k A[m,k] * B[k,n]   (B row-major K x N)
// GATHER: A rows indexed via gidx[z*T_ + m]
// MULTI:  z in {0,1,2} selects (B, bias, C, N) from mp; ldb=ldc=N
// SILU:   epilogue: C[m,n] = silu(C[m,n]) * acc   (read-modify-write)
#define A_PITCH 20      // 16 k + 4 pad
#define B_PITCH 136     // 128 n + 8 pad
#define ABUF (128 * A_PITCH)
#define BBUF (16 * B_PITCH)

template<bool GATHER, bool MULTI, bool SILU>
__global__ __launch_bounds__(256)
void gemm_kernel(const float* __restrict__ A, int lda, long sA,
                 const float* __restrict__ B, int ldb, long sB,
                 const float* __restrict__ bias,
                 float* __restrict__ C, int ldc, long sC,
                 int M, int N, int Kd,
                 const int* __restrict__ cnt, const int* __restrict__ gidx,
                 QKVParams mp)
{
    int z = blockIdx.z;
    if (MULTI) {
        if (z == 0)      { B = mp.B0; bias = mp.bias0; C = mp.C0; N = mp.N0; }
        else if (z == 1) { B = mp.B1; bias = mp.bias1; C = mp.C1; N = mp.N1; }
        else             { B = mp.B2; bias = mp.bias2; C = mp.C2; N = mp.N2; }
        ldb = N; ldc = N;
    } else {
        A += (long)z * sA;
        B += (long)z * sB;
        C += (long)z * sC;
        if (cnt) M = cnt[z];
    }
    const int* rows = GATHER ? (gidx + z * T_) : nullptr;

    int m0 = blockIdx.y * 128;
    int n0 = blockIdx.x * 128;
    if (m0 >= M || n0 >= N) return;

    __shared__ float As[2][ABUF];
    __shared__ float Bs[2][BBUF];

    int tid = threadIdx.x;
    int qa0 = tid, qa1 = tid + 256;

    int aM0 = qa0 >> 2, aK0 = (qa0 & 3) * 4;
    int aM1 = qa1 >> 2, aK1 = (qa1 & 3) * 4;
    bool aok0 = (m0 + aM0) < M;
    bool aok1 = (m0 + aM1) < M;
    long arow0 = 0, arow1 = 0;
    if (aok0) arow0 = GATHER ? (long)rows[m0 + aM0] : (long)(m0 + aM0);
    if (aok1) arow1 = GATHER ? (long)rows[m0 + aM1] : (long)(m0 + aM1);

    int bR0 = qa0 >> 5, bC0 = (qa0 & 31) * 4;
    int bR1 = qa1 >> 5, bC1 = (qa1 & 31) * 4;

    unsigned asb = (unsigned)__cvta_generic_to_shared(&As[0][0]);
    unsigned bsb = (unsigned)__cvta_generic_to_shared(&Bs[0][0]);
    unsigned adst0 = asb + (aM0 * A_PITCH + aK0) * 4;
    unsigned adst1 = asb + (aM1 * A_PITCH + aK1) * 4;
    unsigned bdst0 = bsb + (bR0 * B_PITCH + bC0) * 4;
    unsigned bdst1 = bsb + (bR1 * B_PITCH + bC1) * 4;

    float acc[4][4][4];
#pragma unroll
    for (int i = 0; i < 4; i++)
#pragma unroll
        for (int j = 0; j < 4; j++)
#pragma unroll
            for (int r = 0; r < 4; r++) acc[i][j][r] = 0.f;

    int wid = tid >> 5, lane = tid & 31;
    int lr = lane >> 2, lc = lane & 3;
    int wm = (wid & 1) * 64;
    int wn = (wid >> 1) * 32;

    const int KT = Kd >> 4;

    {
        cp16(adst0, A + arow0 * lda + aK0, aok0);
        cp16(adst1, A + arow1 * lda + aK1, aok1);
        cp16(bdst0, B + (long)bR0 * ldb + n0 + bC0, true);
        cp16(bdst1, B + (long)bR1 * ldb + n0 + bC1, true);
        cp_commit();
    }

    for (int kt = 0; kt < KT; kt++) {
        if (kt + 1 < KT) {
            int k0 = (kt + 1) << 4;
            unsigned off_a = ((kt + 1) & 1) * ABUF * 4;
            unsigned off_b = ((kt + 1) & 1) * BBUF * 4;
            cp16(adst0 + off_a, A + arow0 * lda + k0 + aK0, aok0);
            cp16(adst1 + off_a, A + arow1 * lda + k0 + aK1, aok1);
            cp16(bdst0 + off_b, B + (long)(k0 + bR0) * ldb + n0 + bC0, true);
            cp16(bdst1 + off_b, B + (long)(k0 + bR1) * ldb + n0 + bC1, true);
            cp_commit();
            cp_wait<1>();
        } else {
            cp_wait<0>();
        }
        __syncthreads();

        int buf = kt & 1;
        const float* Ab = As[buf];
        const float* Bb = Bs[buf];

#pragma unroll
        for (int kk = 0; kk < 16; kk += 8) {
            unsigned afr[4][4];
#pragma unroll
            for (int i = 0; i < 4; i++) {
                int mb = wm + i * 16;
                afr[i][0] = f2tf(Ab[(mb + lr)     * A_PITCH + kk + lc]);
                afr[i][1] = f2tf(Ab[(mb + lr + 8) * A_PITCH + kk + lc]);
                afr[i][2] = f2tf(Ab[(mb + lr)     * A_PITCH + kk + lc + 4]);
                afr[i][3] = f2tf(Ab[(mb + lr + 8) * A_PITCH + kk + lc + 4]);
            }
            unsigned bfr[4][2];
#pragma unroll
            for (int j = 0; j < 4; j++) {
                int nb = wn + j * 8;
                bfr[j][0] = f2tf(Bb[(kk + lc)     * B_PITCH + nb + lr]);
                bfr[j][1] = f2tf(Bb[(kk + lc + 4) * B_PITCH + nb + lr]);
            }
#pragma unroll
            for (int i = 0; i < 4; i++)
#pragma unroll
                for (int j = 0; j < 4; j++)
                    mma_tf32(acc[i][j], afr[i][0], afr[i][1], afr[i][2], afr[i][3],
                             bfr[j][0], bfr[j][1]);
        }
        __syncthreads();
    }

    // epilogue
#pragma unroll
    for (int i = 0; i < 4; i++) {
#pragma unroll
        for (int j = 0; j < 4; j++) {
            int m = m0 + wm + i * 16 + lr;
            int n = n0 + wn + j * 8 + lc * 2;
            float bv0 = 0.f, bv1 = 0.f;
            if (bias) { bv0 = bias[n]; bv1 = bias[n + 1]; }
            if (m < M) {
                float v0 = acc[i][j][0] + bv0, v1 = acc[i][j][1] + bv1;
                if (SILU) {
                    float2 g = *(float2*)&C[(long)m * ldc + n];
                    v0 = g.x / (1.f + __expf(-g.x)) * v0;
                    v1 = g.y / (1.f + __expf(-g.y)) * v1;
                }
                *(float2*)&C[(long)m * ldc + n] = make_float2(v0, v1);
            }
            if (m + 8 < M) {
                float v0 = acc[i][j][2] + bv0, v1 = acc[i][j][3] + bv1;
                if (SILU) {
                    float2 g = *(float2*)&C[(long)(m + 8) * ldc + n];
                    v0 = g.x / (1.f + __expf(-g.x)) * v0;
                    v1 = g.y / (1.f + __expf(-g.y)) * v1;
                }
                *(float2*)&C[(long)(m + 8) * ldc + n] = make_float2(v0, v1);
            }
        }
    }
}

// ---------------- flash attention v2: 512 threads / 16 warps ----------------
// Warp (rowg, ch): rowg = wid>>1 owns Q-rows [rowg*16, +16); ch = wid&1 owns a
// 64-wide column half of S (KV rows) and of O (head dims). Row softmax stats
// combine across the ch-pair via smem. Accumulation order per output element
// is identical to the 8-warp version (same kk order, same mma shape) so the
// result is bit-identical.
// smem: Qs | KVs (K then V) | Ps | red[512] — all tf32 bit patterns.
#define FP 132
#define FA_SMEM ((3 * 128 * FP + 512) * 4)

__global__ __launch_bounds__(512)
void flash_attn_kernel(const float* __restrict__ q, const float* __restrict__ k,
                       const float* __restrict__ v, float* __restrict__ attn)
{
    int qi = blockIdx.x;
    int h  = blockIdx.y;
    int kvh = h >> 2;
    extern __shared__ unsigned smu[];
    unsigned* Qs  = smu;
    unsigned* KVs = smu + 128 * FP;
    unsigned* Ps  = smu + 2 * 128 * FP;
    float* redm = (float*)(smu + 3 * 128 * FP);        // [128][2]
    float* reds = redm + 256;                           // [128][2]

    int tid = threadIdx.x, wid = tid >> 5, lane = tid & 31;
    int lr = lane >> 2, lc = lane & 3;
    int rowg = wid >> 1, ch = wid & 1;
    int colbase = ch * 64;
    const float scale = 0.08838834764831845f;

    // load Q tile (convert to tf32 bits once)
    for (int i = tid; i < 128 * 32; i += 512) {
        int r = i >> 5, c4 = (i & 31) * 4;
        float4 val = *(const float4*)&q[((long)(qi * 128 + r) * H_ + h) * HD_ + c4];
        uint4 b = make_uint4(f2tf(val.x), f2tf(val.y), f2tf(val.z), f2tf(val.w));
        *(uint4*)&Qs[r * FP + c4] = b;
    }

    float m_i[2] = {-1e30f, -1e30f};
    float l_i[2] = {0.f, 0.f};
    float o[8][4];
#pragma unroll
    for (int n = 0; n < 8; n++)
#pragma unroll
        for (int r = 0; r < 4; r++) o[n][r] = 0.f;

    int row0 = rowg * 16 + lr;       // local rows: row0, row0+8
    int tg0 = qi * 128 + row0;
    int tg1 = tg0 + 8;

    for (int j = 0; j <= qi; j++) {
        __syncthreads();   // prev iter's PV reads of KVs/Ps done (Q stores iter 0)
        for (int i = tid; i < 128 * 32; i += 512) {
            int r = i >> 5, c4 = (i & 31) * 4;
            float4 val = *(const float4*)&k[((long)(j * 128 + r) * KVH_ + kvh) * HD_ + c4];
            uint4 b = make_uint4(f2tf(val.x), f2tf(val.y), f2tf(val.z), f2tf(val.w));
            *(uint4*)&KVs[r * FP + c4] = b;
        }
        __syncthreads();

        // S = Q @ K^T over this warp's 64-column half
        float s[8][4];
#pragma unroll
        for (int n = 0; n < 8; n++)
#pragma unroll
            for (int r = 0; r < 4; r++) s[n][r] = 0.f;

#pragma unroll
        for (int kk = 0; kk < 128; kk += 8) {
            unsigned a0 = Qs[row0 * FP + kk + lc];
            unsigned a1 = Qs[(row0 + 8) * FP + kk + lc];
            unsigned a2 = Qs[row0 * FP + kk + lc + 4];
            unsigned a3 = Qs[(row0 + 8) * FP + kk + lc + 4];
#pragma unroll
            for (int n = 0; n < 8; n++) {
                unsigned b0 = KVs[(colbase + n * 8 + lr) * FP + kk + lc];
                unsigned b1 = KVs[(colbase + n * 8 + lr) * FP + kk + lc + 4];
                mma_tf32(s[n], a0, a1, a2, a3, b0, b1);
            }
        }

        // scale + causal mask
        if (j == qi) {
#pragma unroll
            for (int n = 0; n < 8; n++) {
                int c0 = j * 128 + colbase + n * 8 + lc * 2;
                s[n][0] = (c0     <= tg0) ? s[n][0] * scale : -1e30f;
                s[n][1] = (c0 + 1 <= tg0) ? s[n][1] * scale : -1e30f;
                s[n][2] = (c0     <= tg1) ? s[n][2] * scale : -1e30f;
                s[n][3] = (c0 + 1 <= tg1) ? s[n][3] * scale : -1e30f;
            }
        } else {
#pragma unroll
            for (int n = 0; n < 8; n++)
#pragma unroll
                for (int r = 0; r < 4; r++) s[n][r] *= scale;
        }

        // partial row max over this 64-col half
        float pm0 = -1e30f, pm1 = -1e30f;
#pragma unroll
        for (int n = 0; n < 8; n++) {
            pm0 = fmaxf(pm0, fmaxf(s[n][0], s[n][1]));
            pm1 = fmaxf(pm1, fmaxf(s[n][2], s[n][3]));
        }
        pm0 = fmaxf(pm0, __shfl_xor_sync(0xffffffffu, pm0, 1));
        pm0 = fmaxf(pm0, __shfl_xor_sync(0xffffffffu, pm0, 2));
        pm1 = fmaxf(pm1, __shfl_xor_sync(0xffffffffu, pm1, 1));
        pm1 = fmaxf(pm1, __shfl_xor_sync(0xffffffffu, pm1, 2));
        if (lc == 0) {
            redm[row0 * 2 + ch]       = pm0;
            redm[(row0 + 8) * 2 + ch] = pm1;
        }
        __syncthreads();   // redm visible; also: all S-mma done -> KVs dead (K)

        float gm0 = fmaxf(redm[row0 * 2],       redm[row0 * 2 + 1]);
        float gm1 = fmaxf(redm[(row0 + 8) * 2], redm[(row0 + 8) * 2 + 1]);

        float mn0 = fmaxf(m_i[0], gm0);
        float mn1 = fmaxf(m_i[1], gm1);
        float al0 = __expf(m_i[0] - mn0);
        float al1 = __expf(m_i[1] - mn1);
        m_i[0] = mn0; m_i[1] = mn1;

        float rs0 = 0.f, rs1 = 0.f;
#pragma unroll
        for (int n = 0; n < 8; n++) {
            s[n][0] = __expf(s[n][0] - mn0);
            s[n][1] = __expf(s[n][1] - mn0);
            s[n][2] = __expf(s[n][2] - mn1);
            s[n][3] = __expf(s[n][3] - mn1);
            rs0 += s[n][0] + s[n][1];
            rs1 += s[n][2] + s[n][3];
        }
        rs0 += __shfl_xor_sync(0xffffffffu, rs0, 1);
        rs0 += __shfl_xor_sync(0xffffffffu, rs0, 2);
        rs1 += __shfl_xor_sync(0xffffffffu, rs1, 1);
        rs1 += __shfl_xor_sync(0xffffffffu, rs1, 2);
        if (lc == 0) {
            reds[row0 * 2 + ch]       = rs0;
            reds[(row0 + 8) * 2 + ch] = rs1;
        }

        // V load (KVs is dead for K after the redm barrier)
        for (int i = tid; i < 128 * 32; i += 512) {
            int r = i >> 5, c4 = (i & 31) * 4;
            float4 val = *(const float4*)&v[((long)(j * 128 + r) * KVH_ + kvh) * HD_ + c4];
            uint4 b = make_uint4(f2tf(val.x), f2tf(val.y), f2tf(val.z), f2tf(val.w));
            *(uint4*)&KVs[r * FP + c4] = b;
        }

        // write P (tf32 bits) — this warp's rows x its 64-col half
#pragma unroll
        for (int n = 0; n < 8; n++) {
            *(uint2*)&Ps[row0 * FP + colbase + n * 8 + lc * 2] =
                make_uint2(f2tf(s[n][0]), f2tf(s[n][1]));
            *(uint2*)&Ps[(row0 + 8) * FP + colbase + n * 8 + lc * 2] =
                make_uint2(f2tf(s[n][2]), f2tf(s[n][3]));
        }
        __syncthreads();   // reds + Ps + V all visible

        float gs0 = reds[row0 * 2]       + reds[row0 * 2 + 1];
        float gs1 = reds[(row0 + 8) * 2] + reds[(row0 + 8) * 2 + 1];
        l_i[0] = l_i[0] * al0 + gs0;
        l_i[1] = l_i[1] * al1 + gs1;

#pragma unroll
        for (int n = 0; n < 8; n++) {
            o[n][0] *= al0; o[n][1] *= al0;
            o[n][2] *= al1; o[n][3] *= al1;
        }

        // O += P @ V : full 128 s-range, this warp's 64 output dims
#pragma unroll
        for (int kk = 0; kk < 128; kk += 8) {
            unsigned a0 = Ps[row0 * FP + kk + lc];
            unsigned a1 = Ps[(row0 + 8) * FP + kk + lc];
            unsigned a2 = Ps[row0 * FP + kk + lc + 4];
            unsigned a3 = Ps[(row0 + 8) * FP + kk + lc + 4];
#pragma unroll
            for (int n = 0; n < 8; n++) {
                unsigned b0 = KVs[(kk + lc) * FP + colbase + n * 8 + lr];
                unsigned b1 = KVs[(kk + lc + 4) * FP + colbase + n * 8 + lr];
                mma_tf32(o[n], a0, a1, a2, a3, b0, b1);
            }
        }
    }

    float inv0 = 1.f / l_i[0];
    float inv1 = 1.f / l_i[1];
#pragma unroll
    for (int n = 0; n < 8; n++) {
        int c = colbase + n * 8 + lc * 2;
        *(float2*)&attn[((long)tg0 * H_ + h) * HD_ + c] =
            make_float2(o[n][0] * inv0, o[n][1] * inv0);
        *(float2*)&attn[((long)tg1 * H_ + h) * HD_ + c] =
            make_float2(o[n][2] * inv1, o[n][3] * inv1);
    }
}

// ---------------- small fused kernels (float4 vectorized) ----------------
__global__ void rmsnorm_kernel(const float* __restrict__ x, const float* __restrict__ w,
                               float* __restrict__ out, int* __restrict__ cnt)
{
    int t = blockIdx.x, tid = threadIdx.x;
    if (t == 0 && tid < E_) cnt[tid] = 0;
    __shared__ float red[256];
    const float4* row = (const float4*)(x + (long)t * D_);
    float4 v0 = row[tid], v1 = row[tid + 256];
    float s = v0.x * v0.x + v0.y * v0.y + v0.z * v0.z + v0.w * v0.w
            + v1.x * v1.x + v1.y * v1.y + v1.z * v1.z + v1.w * v1.w;
    red[tid] = s; __syncthreads();
    for (int o = 128; o > 0; o >>= 1) { if (tid < o) red[tid] += red[tid + o]; __syncthreads(); }
    float inv = rsqrtf(red[0] / (float)D_ + 1e-6f);
    const float4* wr = (const float4*)w;
    float4 w0 = wr[tid], w1 = wr[tid + 256];
    float4* orow = (float4*)(out + (long)t * D_);
    orow[tid]       = make_float4(v0.x * inv * w0.x, v0.y * inv * w0.y,
                                  v0.z * inv * w0.z, v0.w * inv * w0.w);
    orow[tid + 256] = make_float4(v1.x * inv * w1.x, v1.y * inv * w1.y,
                                  v1.z * inv * w1.z, v1.w * inv * w1.w);
}

__global__ void add_rms_kernel(const float* __restrict__ hid, const float* __restrict__ ao,
                               const float* __restrict__ w,
                               float* __restrict__ h1, float* __restrict__ xn2)
{
    int t = blockIdx.x, tid = threadIdx.x;
    __shared__ float red[256];
    const float4* hr = (const float4*)(hid + (long)t * D_);
    const float4* ar = (const float4*)(ao + (long)t * D_);
    float4 a0 = hr[tid], a1 = hr[tid + 256];
    float4 b0 = ar[tid], b1 = ar[tid + 256];
    float4 v0 = make_float4(a0.x + b0.x, a0.y + b0.y, a0.z + b0.z, a0.w + b0.w);
    float4 v1 = make_float4(a1.x + b1.x, a1.y + b1.y, a1.z + b1.z, a1.w + b1.w);
    float4* h1r = (float4*)(h1 + (long)t * D_);
    h1r[tid] = v0; h1r[tid + 256] = v1;
    float s = v0.x * v0.x + v0.y * v0.y + v0.z * v0.z + v0.w * v0.w
            + v1.x * v1.x + v1.y * v1.y + v1.z * v1.z + v1.w * v1.w;
    red[tid] = s; __syncthreads();
    for (int o = 128; o > 0; o >>= 1) { if (tid < o) red[tid] += red[tid + o]; __syncthreads(); }
    float inv = rsqrtf(red[0] / (float)D_ + 1e-6f);
    const float4* wr = (const float4*)w;
    float4 w0 = wr[tid], w1 = wr[tid + 256];
    float4* xr = (float4*)(xn2 + (long)t * D_);
    xr[tid]       = make_float4(v0.x * inv * w0.x, v0.y * inv * w0.y,
                                v0.z * inv * w0.z, v0.w * inv * w0.w);
    xr[tid + 256] = make_float4(v1.x * inv * w1.x, v1.y * inv * w1.y,
                                v1.z * inv * w1.z, v1.w * inv * w1.w);
}

// one launch for both q and k rope
__global__ void rope_kernel(float* __restrict__ q, float* __restrict__ kk,
                            const int* __restrict__ pos)
{
    int i = blockIdx.x * blockDim.x + threadIdx.x;
    const int totq = T_ * H_ * 64;
    float* x; int nh;
    if (i < totq) { x = q; nh = H_; }
    else {
        i -= totq;
        if (i >= T_ * KVH_ * 64) return;
        x = kk; nh = KVH_;
    }
    int d = i & 63;
    int rest = i >> 6;
    int h = rest % nh;
    int t = rest / nh;
    float inv = exp2f(-(float)d * 0.31143075895f);  // theta^(-d/64)
    float fr = (float)pos[t] * inv;
    float s, c;
    sincosf(fr, &s, &c);
    long base = ((long)t * nh + h) * HD_;
    float x1 = x[base + d], x2 = x[base + 64 + d];
    x[base + d]      = x1 * c - x2 * s;
    x[base + 64 + d] = x2 * c + x1 * s;
}

__global__ void router_kernel(const float* __restrict__ x, const float* __restrict__ gw,
                              int* __restrict__ cnt, int* __restrict__ idx,
                              int* __restrict__ slot, float* __restrict__ wt)
{
    int t = blockIdx.x, tid = threadIdx.x;
    __shared__ float red[256];
    __shared__ float sl[E_];
    float l[E_];
#pragma unroll
    for (int e = 0; e < E_; e++) l[e] = 0.f;
    const float* row = x + (long)t * D_;
    for (int d = tid; d < D_; d += 256) {
        float xv = row[d];
#pragma unroll
        for (int e = 0; e < E_; e++) l[e] += xv * gw[d * E_ + e];
    }
    for (int e = 0; e < E_; e++) {
        red[tid] = l[e]; __syncthreads();
        for (int o = 128; o > 0; o >>= 1) { if (tid < o) red[tid] += red[tid + o]; __syncthreads(); }
        if (tid == 0) sl[e] = red[0];
        __syncthreads();
    }
    if (tid == 0) {
        float mx = sl[0];
        for (int e = 1; e < E_; e++) mx = fmaxf(mx, sl[e]);
        float p[E_]; float s = 0.f;
        for (int e = 0; e < E_; e++) { p[e] = expf(sl[e] - mx); s += p[e]; }
        for (int e = 0; e < E_; e++) p[e] /= s;
        int e0 = 0;
        for (int e = 1; e < E_; e++) if (p[e] > p[e0]) e0 = e;
        int e1 = -1;
        for (int e = 0; e < E_; e++) { if (e == e0) continue; if (e1 < 0 || p[e] > p[e1]) e1 = e; }
        float w0 = p[e0], w1 = p[e1], ws = w0 + w1;
        w0 /= ws; w1 /= ws;
        int p0 = atomicAdd(&cnt[e0], 1);
        idx[e0 * T_ + p0] = t; slot[2 * t] = e0 * T_ + p0; wt[2 * t] = w0;
        int p1 = atomicAdd(&cnt[e1], 1);
        idx[e1 * T_ + p1] = t; slot[2 * t + 1] = e1 * T_ + p1; wt[2 * t + 1] = w1;
    }
}

__global__ void combine_kernel(const float* __restrict__ h1, const float* __restrict__ y,
                               const int* __restrict__ slot, const float* __restrict__ wt,
                               float* __restrict__ out)
{
    int t = blockIdx.x, tid = threadIdx.x;
    long s0 = slot[2 * t], s1 = slot[2 * t + 1];
    float w0 = wt[2 * t], w1 = wt[2 * t + 1];
    const float4* hr = (const float4*)(h1 + (long)t * D_);
    const float4* y0 = (const float4*)(y + s0 * D_);
    const float4* y1 = (const float4*)(y + s1 * D_);
    float4* orow = (float4*)(out + (long)t * D_);
#pragma unroll
    for (int it = 0; it < 2; it++) {
        int d = tid + it * 256;
        float4 hv = hr[d], a = y0[d], b = y1[d];
        orow[d] = make_float4(hv.x + w0 * a.x + w1 * b.x,
                              hv.y + w0 * a.y + w1 * b.y,
                              hv.z + w0 * a.z + w1 * b.z,
                              hv.w + w0 * a.w + w1 * b.w);
    }
}

// ---------------- launch ----------------
extern "C" void kernel_launch(void* const* d_in, const int* in_sizes, int n_in,
                              void* d_out, int out_size)
{
    const float* hidden = (const float*)d_in[0];
    const int*   pos    = (const int*)  d_in[1];
    const float* ln1    = (const float*)d_in[2];
    const float* ln2    = (const float*)d_in[3];
    const float* wq     = (const float*)d_in[4];
    const float* bq     = (const float*)d_in[5];
    const float* wk     = (const float*)d_in[6];
    const float* bk     = (const float*)d_in[7];
    const float* wv     = (const float*)d_in[8];
    const float* bv     = (const float*)d_in[9];
    const float* wo     = (const float*)d_in[10];
    const float* gatew  = (const float*)d_in[11];
    const float* wgate  = (const float*)d_in[12];
    const float* wup    = (const float*)d_in[13];
    const float* wdown  = (const float*)d_in[14];
    float* out = (float*)d_out;

    float *xn, *q, *k, *v, *attn, *h1, *xn2, *gg, *yy, *wt;
    int *cnt, *idx, *slot;
    cudaGetSymbolAddress((void**)&xn,   g_xn);
    cudaGetSymbolAddress((void**)&q,    g_q);
    cudaGetSymbolAddress((void**)&k,    g_k);
    cudaGetSymbolAddress((void**)&v,    g_v);
    cudaGetSymbolAddress((void**)&attn, g_attn);
    cudaGetSymbolAddress((void**)&h1,   g_h1);
    cudaGetSymbolAddress((void**)&xn2,  g_xn2);
    cudaGetSymbolAddress((void**)&gg,   g_g);
    cudaGetSymbolAddress((void**)&yy,   g_y);
    cudaGetSymbolAddress((void**)&cnt,  g_cnt);
    cudaGetSymbolAddress((void**)&idx,  g_idx);
    cudaGetSymbolAddress((void**)&slot, g_slot);
    cudaGetSymbolAddress((void**)&wt,   g_wt);

    static int fa_attr_set = 0;
    if (!fa_attr_set) {
        cudaFuncSetAttribute(flash_attn_kernel,
                             cudaFuncAttributeMaxDynamicSharedMemorySize, FA_SMEM);
        fa_attr_set = 1;
    }

    QKVParams dummy = {};
    dim3 blk(256);

    // x = rmsnorm(hidden) * ln1  (also zeroes cnt)
    rmsnorm_kernel<<<T_, 256>>>(hidden, ln1, xn, cnt);

    // fused QKV projection (+bias): one launch, z selects segment
    QKVParams qkv;
    qkv.B0 = wq; qkv.B1 = wk; qkv.B2 = wv;
    qkv.bias0 = bq; qkv.bias1 = bk; qkv.bias2 = bv;
    qkv.C0 = q; qkv.C1 = k; qkv.C2 = v;
    qkv.N0 = H_ * HD_; qkv.N1 = KVH_ * HD_; qkv.N2 = KVH_ * HD_;
    gemm_kernel<false, true, false><<<dim3(16, 16, 3), blk>>>(
        xn, D_, 0, nullptr, 0, 0, nullptr, nullptr, 0, 0,
        T_, 0, D_, nullptr, nullptr, qkv);

    // RoPE (q and k in one launch)
    rope_kernel<<<(T_ * (H_ + KVH_) * 64 + 255) / 256, 256>>>(q, k, pos);

    // flash attention (fused QK^T + softmax + PV, causal), 512 threads
    flash_attn_kernel<<<dim3(16, 16), 512, FA_SMEM>>>(q, k, v, attn);

    // O projection -> xn (scratch reuse)
    gemm_kernel<false, false, false><<<dim3(16, 16, 1), blk>>>(
        attn, H_ * HD_, 0, wo, D_, 0, nullptr, xn, D_, 0,
        T_, D_, H_ * HD_, nullptr, nullptr, dummy);

    // h1 = hidden + attn_out ; xn2 = rmsnorm(h1) * ln2
    add_rms_kernel<<<T_, 256>>>(hidden, xn, ln2, h1, xn2);

    // router: top-2 experts per token
    router_kernel<<<T_, 256>>>(xn2, gatew, cnt, idx, slot, wt);

    // gate proj (gathered)
    gemm_kernel<true, false, false><<<dim3(8, 16, E_), blk>>>(
        xn2, D_, 0, wgate, I_, (long)D_ * I_, nullptr, gg, I_, (long)T_ * I_,
        T_, I_, D_, cnt, idx, dummy);

    // up proj (gathered) with fused ff = silu(g) * u written into gg
    gemm_kernel<true, false, true><<<dim3(8, 16, E_), blk>>>(
        xn2, D_, 0, wup, I_, (long)D_ * I_, nullptr, gg, I_, (long)T_ * I_,
        T_, I_, D_, cnt, idx, dummy);

    // y_e = ff_e @ Wd[e]
    gemm_kernel<false, false, false><<<dim3(16, 16, E_), blk>>>(
        gg, I_, (long)T_ * I_, wdown, D_, (long)I_ * D_, nullptr, yy, D_, (long)T_ * D_,
        T_, D_, I_, cnt, nullptr, dummy);

    // out = h1 + w0*y[slot0] + w1*y[slot1]
    combine_kernel<<<T_, 256>>>(h1, yy, slot, wt, out);
}